// round 5
// baseline (speedup 1.0000x reference)
#include <cuda_runtime.h>
#include <cuda_bf16.h>
#include <cstdint>
#include <math.h>

#define EDIM   512
#define TSTEPS 8
#define NWIN   8192
#define XROWS  65536
#define KSTORE 1024            // A/H stored as [hi(512) | lo(512)]
#define KSPLIT 1536            // logical K'' (3 products); W stored [wh|wl|wh]
#define BK     64              // bf16 K per smem tile
#define NKIT   (KSPLIT / BK)   // 24
#define ROWB   144             // padded smem row stride (128B data + 16B pad)
#define TILEB  (128 * ROWB)    // 18432 B per operand tile
#define STAGEB (2 * TILEB)     // 36864
#define NSTAGE 3
#define SMEMB  (NSTAGE * STAGEB)   // 110592

// ---------------- scratch (device globals) ----------------------------------
__device__ __nv_bfloat16 g_xs[(size_t)XROWS * KSTORE];      // 134 MB
__device__ __nv_bfloat16 g_ws[2][(size_t)EDIM * KSPLIT];    // 2 x 1.5 MB
__device__ __nv_bfloat16 g_hs[2][(size_t)NWIN * KSTORE];    // 2 x 16.8 MB
__device__ float         g_pre[(size_t)XROWS * EDIM];       // 134 MB

// ---------------- helpers ----------------------------------------------------
__device__ __forceinline__ uint32_t smem_u32(const void* p) {
    uint32_t a;
    asm("{ .reg .u64 t; cvta.to.shared.u64 t, %1; cvt.u32.u64 %0, t; }"
        : "=r"(a) : "l"(p));
    return a;
}
__device__ __forceinline__ void cp16(uint32_t saddr, const void* gaddr) {
    asm volatile("cp.async.cg.shared.global [%0], [%1], 16;"
                 :: "r"(saddr), "l"(gaddr) : "memory");
}
__device__ __forceinline__ void cp_commit() {
    asm volatile("cp.async.commit_group;" ::: "memory");
}
template <int N>
__device__ __forceinline__ void cp_wait() {
    asm volatile("cp.async.wait_group %0;" :: "n"(N) : "memory");
}
__device__ __forceinline__ void ldsm4(uint32_t& r0, uint32_t& r1, uint32_t& r2,
                                      uint32_t& r3, uint32_t addr) {
    asm volatile("ldmatrix.sync.aligned.m8n8.x4.shared.b16 {%0,%1,%2,%3}, [%4];"
                 : "=r"(r0), "=r"(r1), "=r"(r2), "=r"(r3) : "r"(addr));
}
__device__ __forceinline__ void mma16816(float* c, const uint32_t* a,
                                         uint32_t b0, uint32_t b1) {
    asm volatile("mma.sync.aligned.m16n8k16.row.col.f32.bf16.bf16.f32 "
                 "{%0,%1,%2,%3}, {%4,%5,%6,%7}, {%8,%9}, {%0,%1,%2,%3};"
                 : "+f"(c[0]), "+f"(c[1]), "+f"(c[2]), "+f"(c[3])
                 : "r"(a[0]), "r"(a[1]), "r"(a[2]), "r"(a[3]), "r"(b0), "r"(b1));
}
__device__ __forceinline__ void split2(float v, __nv_bfloat16& hi, __nv_bfloat16& lo) {
    hi = __float2bfloat16(v);
    lo = __float2bfloat16(v - __bfloat162float(hi));
}

// ---------------- prep kernels ----------------------------------------------
__global__ __launch_bounds__(256)
void prep_w(const float* __restrict__ wih, const float* __restrict__ whh) {
    int idx = blockIdx.x * 256 + threadIdx.x;           // 0 .. 2*512*512-1
    int which = idx >> 18;
    int e = idx & 262143;
    int n = e >> 9, k = e & 511;
    const float* src = which ? whh : wih;
    __nv_bfloat16 hi, lo;
    split2(src[n * 512 + k], hi, lo);
    __nv_bfloat16* dst = g_ws[which] + (size_t)n * KSPLIT;
    dst[k] = hi; dst[512 + k] = lo; dst[1024 + k] = hi;
}

__global__ __launch_bounds__(256)
void prep_x(const float* __restrict__ x) {
    size_t idx = (size_t)blockIdx.x * 256 + threadIdx.x;  // over 65536*128 float4
    size_t row = idx >> 7;
    int q = (int)(idx & 127);
    float4 v = ((const float4*)x)[idx];
    __nv_bfloat16 h0,h1,h2,h3,l0,l1,l2,l3;
    split2(v.x,h0,l0); split2(v.y,h1,l1); split2(v.z,h2,l2); split2(v.w,h3,l3);
    __nv_bfloat16* base = g_xs + row * KSTORE + q * 4;
    *(__nv_bfloat162*)(base)       = __nv_bfloat162{h0,h1};
    *(__nv_bfloat162*)(base + 2)   = __nv_bfloat162{h2,h3};
    *(__nv_bfloat162*)(base + 512) = __nv_bfloat162{l0,l1};
    *(__nv_bfloat162*)(base + 514) = __nv_bfloat162{l2,l3};
}

// ---------------- bf16x3 HMMA GEMM ------------------------------------------
// C[m][n] = sum over K''=1536 of A''[m][k]*W''[n][k]; A'' 64-chunk c maps to
// stored chunk (c<8 ? c : c-8) of the [hi|lo] layout (A'' = [ah, ah, al];
// W'' = [wh, wl, wh]).
// mode 0: g_pre = acc + bias; t=0 rows also write tanh-split H0
// mode 1: h = tanh(acc + pre_t); split-bf16 h out (fp32 out at t=7)
__global__ __launch_bounds__(256, 2)
void gemm_bf16x3(const __nv_bfloat16* __restrict__ A,
                 const __nv_bfloat16* __restrict__ Bw,
                 const float* __restrict__ b0, const float* __restrict__ b1,
                 float* __restrict__ outp, __nv_bfloat16* __restrict__ hs_out,
                 __nv_bfloat16* __restrict__ h0_out,
                 int mode, int t)
{
    extern __shared__ __align__(16) char dyn[];   // NSTAGE x [A:18432 | B:18432]
    __shared__ float s_bias[128];

    const int tid = threadIdx.x;
    const int wid = tid >> 5;
    const int lane = tid & 31;
    const int warpM = wid & 3;
    const int warpN = wid >> 2;
    const int bm = blockIdx.y * 128;
    const int bn = blockIdx.x * 128;

    const uint32_t sbase = smem_u32(dyn);

    if (mode == 0 && tid < 128) s_bias[tid] = b0[bn + tid] + b1[bn + tid];

    // Loader: row = tid>>1 (0..127), 4 contiguous 16B chunks at (tid&1)*64B.
    const int l_row = tid >> 1;
    const int l_c4  = (tid & 1) * 4;        // first uint4 within the 8-uint4 row
    const uint4* A4 = (const uint4*)A;      // row stride 128 uint4 (KSTORE)
    const uint4* B4 = (const uint4*)Bw;     // row stride 192 uint4 (KSPLIT)
    const uint4* Ap = &A4[(size_t)(bm + l_row) * 128 + l_c4];
    const uint4* Bp = &B4[(size_t)(bn + l_row) * 192 + l_c4];
    const uint32_t sRow = (uint32_t)(l_row * ROWB + l_c4 * 16);

    // ldmatrix lane offsets
    const int g = lane >> 3;
    uint32_t a_off[2], b_off[4];
    #pragma unroll
    for (int mt = 0; mt < 2; mt++)
        a_off[mt] = (uint32_t)((warpM * 32 + mt * 16 + (g & 1) * 8 + (lane & 7)) * ROWB
                               + (g >> 1) * 16);
    #pragma unroll
    for (int np = 0; np < 4; np++)
        b_off[np] = (uint32_t)((warpN * 64 + np * 16 + (g >> 1) * 8 + (lane & 7)) * ROWB
                               + (g & 1) * 16);

    float acc[2][8][4];
    #pragma unroll
    for (int i = 0; i < 2; i++)
        #pragma unroll
        for (int j = 0; j < 8; j++)
            #pragma unroll
            for (int q = 0; q < 4; q++) acc[i][j][q] = 0.0f;

    // ---- prologue: fill stages 0..NSTAGE-2
    #pragma unroll
    for (int s = 0; s < NSTAGE - 1; s++) {
        const uint32_t st = sbase + s * STAGEB;
        const int ka = (s < 8 ? s : s - 8) * 8;
        const int kb = s * 8;
        #pragma unroll
        for (int j = 0; j < 4; j++) {
            cp16(st + sRow + j * 16,         Ap + ka + j);
            cp16(st + TILEB + sRow + j * 16, Bp + kb + j);
        }
        cp_commit();
    }

    int st_cur = 0, st_nxt = NSTAGE - 1;
    for (int c = 0; c < NKIT; c++) {
        cp_wait<NSTAGE - 2>();
        __syncthreads();

        const int cn = c + NSTAGE - 1;
        if (cn < NKIT) {
            const uint32_t st = sbase + st_nxt * STAGEB;
            const int ka = (cn < 8 ? cn : cn - 8) * 8;
            const int kb = cn * 8;
            #pragma unroll
            for (int j = 0; j < 4; j++) {
                cp16(st + sRow + j * 16,         Ap + ka + j);
                cp16(st + TILEB + sRow + j * 16, Bp + kb + j);
            }
        }
        cp_commit();
        if (++st_nxt == NSTAGE) st_nxt = 0;

        const uint32_t ab = sbase + st_cur * STAGEB;
        const uint32_t bb = ab + TILEB;
        if (++st_cur == NSTAGE) st_cur = 0;

        #pragma unroll
        for (int kk = 0; kk < 4; kk++) {
            uint32_t afr[2][4];
            #pragma unroll
            for (int mt = 0; mt < 2; mt++)
                ldsm4(afr[mt][0], afr[mt][1], afr[mt][2], afr[mt][3],
                      ab + a_off[mt] + kk * 32);
            #pragma unroll
            for (int np = 0; np < 4; np++) {
                uint32_t r0, r1, r2, r3;
                ldsm4(r0, r1, r2, r3, bb + b_off[np] + kk * 32);
                #pragma unroll
                for (int mt = 0; mt < 2; mt++) {
                    mma16816(acc[mt][np * 2],     afr[mt], r0, r1);
                    mma16816(acc[mt][np * 2 + 1], afr[mt], r2, r3);
                }
            }
        }
    }

    // ---- epilogue --------------------------------------------------------
    const int r_in = lane >> 2;
    const int c_in = (lane & 3) * 2;
    #pragma unroll
    for (int mt = 0; mt < 2; mt++) {
        const int m0 = bm + warpM * 32 + mt * 16 + r_in;   // and m0+8
        #pragma unroll
        for (int nt = 0; nt < 8; nt++) {
            const int nb = bn + warpN * 64 + nt * 8 + c_in;
            float v00 = acc[mt][nt][0], v01 = acc[mt][nt][1];
            float v10 = acc[mt][nt][2], v11 = acc[mt][nt][3];
            if (mode == 0) {
                const float bia0 = s_bias[nb - bn], bia1 = s_bias[nb - bn + 1];
                v00 += bia0; v01 += bia1; v10 += bia0; v11 += bia1;
                *(float2*)(g_pre + (size_t)m0 * EDIM + nb)       = make_float2(v00, v01);
                *(float2*)(g_pre + (size_t)(m0 + 8) * EDIM + nb) = make_float2(v10, v11);
                if ((m0 & 7) == 0) {
                    #pragma unroll
                    for (int h = 0; h < 2; h++) {
                        const size_t w = (size_t)(m0 + 8 * h) >> 3;
                        float a0 = tanhf(h ? v10 : v00);
                        float a1 = tanhf(h ? v11 : v01);
                        __nv_bfloat16 x0,x1,y0,y1;
                        split2(a0, x0, y0); split2(a1, x1, y1);
                        __nv_bfloat16* hd = h0_out + w * KSTORE + nb;
                        *(__nv_bfloat162*)(hd)       = __nv_bfloat162{x0, x1};
                        *(__nv_bfloat162*)(hd + 512) = __nv_bfloat162{y0, y1};
                    }
                }
            } else {
                #pragma unroll
                for (int h = 0; h < 2; h++) {
                    const int m = m0 + 8 * h;
                    float2 pr = *(const float2*)(g_pre + ((size_t)m * TSTEPS + t) * EDIM + nb);
                    float a0 = tanhf((h ? v10 : v00) + pr.x);
                    float a1 = tanhf((h ? v11 : v01) + pr.y);
                    if (t == TSTEPS - 1) {
                        *(float2*)(outp + (size_t)m * EDIM + nb) = make_float2(a0, a1);
                    } else {
                        __nv_bfloat16 x0,x1,y0,y1;
                        split2(a0, x0, y0); split2(a1, x1, y1);
                        __nv_bfloat16* hd = hs_out + (size_t)m * KSTORE + nb;
                        *(__nv_bfloat162*)(hd)       = __nv_bfloat162{x0, x1};
                        *(__nv_bfloat162*)(hd + 512) = __nv_bfloat162{y0, y1};
                    }
                }
            }
        }
    }
}

// ---------------- host ------------------------------------------------------
extern "C" void kernel_launch(void* const* d_in, const int* in_sizes, int n_in,
                              void* d_out, int out_size)
{
    (void)in_sizes; (void)n_in; (void)out_size;
    const float* x    = (const float*)d_in[0];
    const float* W_ih = (const float*)d_in[1];
    const float* W_hh = (const float*)d_in[2];
    const float* b_ih = (const float*)d_in[3];
    const float* b_hh = (const float*)d_in[4];
    float* out = (float*)d_out;

    static __nv_bfloat16* p_xs = nullptr;
    static __nv_bfloat16* p_ws[2];
    static __nv_bfloat16* p_hs[2];
    if (!p_xs) {
        void* p;
        cudaGetSymbolAddress(&p, g_xs); p_xs = (__nv_bfloat16*)p;
        cudaGetSymbolAddress(&p, g_ws);
        p_ws[0] = (__nv_bfloat16*)p;
        p_ws[1] = p_ws[0] + (size_t)EDIM * KSPLIT;
        cudaGetSymbolAddress(&p, g_hs);
        p_hs[0] = (__nv_bfloat16*)p;
        p_hs[1] = p_hs[0] + (size_t)NWIN * KSTORE;
        cudaFuncSetAttribute(gemm_bf16x3,
                             cudaFuncAttributeMaxDynamicSharedMemorySize, SMEMB);
    }

    prep_w<<<2048, 256>>>(W_ih, W_hh);
    prep_x<<<32768, 256>>>(x);

    // pre = X'' @ Wih''^T + bias ; fused H0 for t=0 rows
    gemm_bf16x3<<<dim3(4, 512), 256, SMEMB>>>(p_xs, p_ws[0], b_ih, b_hh,
                                              nullptr, nullptr, p_hs[0], 0, 0);

    for (int t = 1; t < TSTEPS; t++) {
        gemm_bf16x3<<<dim3(4, 64), 256, SMEMB>>>(
            p_hs[(t - 1) & 1], p_ws[1], nullptr, nullptr,
            (t == TSTEPS - 1) ? out : nullptr, p_hs[t & 1], nullptr, 1, t);
    }
}

// round 6
// speedup vs baseline: 1.2519x; 1.2519x over previous
#include <cuda_runtime.h>
#include <cuda_bf16.h>
#include <cstdint>
#include <math.h>

#define EDIM   512
#define TSTEPS 8
#define NWIN   8192
#define XROWS  65536
#define KSTORE 1024            // A/H stored as [hi(512) | lo(512)]
#define KSPLIT 1536            // logical K'' (3 products); W stored [wh|wl|wh]
#define BK     32              // bf16 K per smem tile
#define NKIT   (KSPLIT / BK)   // 48
#define ROWB   80              // padded smem row stride (64B data + 16B pad)
#define TILEB  (128 * ROWB)    // 10240 B per operand tile
#define STAGEB (2 * TILEB)     // A+B per stage = 20480
#define NSTAGE 5
#define SMEMB  (NSTAGE * STAGEB)   // 102400

// ---------------- scratch (device globals) ----------------------------------
__device__ __nv_bfloat16 g_xs[(size_t)XROWS * KSTORE];      // 134 MB
__device__ __nv_bfloat16 g_ws[2][(size_t)EDIM * KSPLIT];    // 2 x 1.5 MB
__device__ __nv_bfloat16 g_hs[2][(size_t)NWIN * KSTORE];    // 2 x 16.8 MB
__device__ float         g_pre[(size_t)XROWS * EDIM];       // 134 MB

// ---------------- helpers ----------------------------------------------------
__device__ __forceinline__ uint32_t smem_u32(const void* p) {
    uint32_t a;
    asm("{ .reg .u64 t; cvta.to.shared.u64 t, %1; cvt.u32.u64 %0, t; }"
        : "=r"(a) : "l"(p));
    return a;
}
__device__ __forceinline__ void cp16(uint32_t saddr, const void* gaddr) {
    asm volatile("cp.async.cg.shared.global [%0], [%1], 16;"
                 :: "r"(saddr), "l"(gaddr) : "memory");
}
__device__ __forceinline__ void cp_commit() {
    asm volatile("cp.async.commit_group;" ::: "memory");
}
template <int N>
__device__ __forceinline__ void cp_wait() {
    asm volatile("cp.async.wait_group %0;" :: "n"(N) : "memory");
}
__device__ __forceinline__ void ldsm4(uint32_t& r0, uint32_t& r1, uint32_t& r2,
                                      uint32_t& r3, uint32_t addr) {
    asm volatile("ldmatrix.sync.aligned.m8n8.x4.shared.b16 {%0,%1,%2,%3}, [%4];"
                 : "=r"(r0), "=r"(r1), "=r"(r2), "=r"(r3) : "r"(addr));
}
__device__ __forceinline__ void mma16816(float* c, const uint32_t* a,
                                         uint32_t b0, uint32_t b1) {
    asm volatile("mma.sync.aligned.m16n8k16.row.col.f32.bf16.bf16.f32 "
                 "{%0,%1,%2,%3}, {%4,%5,%6,%7}, {%8,%9}, {%0,%1,%2,%3};"
                 : "+f"(c[0]), "+f"(c[1]), "+f"(c[2]), "+f"(c[3])
                 : "r"(a[0]), "r"(a[1]), "r"(a[2]), "r"(a[3]), "r"(b0), "r"(b1));
}
__device__ __forceinline__ void split2(float v, __nv_bfloat16& hi, __nv_bfloat16& lo) {
    hi = __float2bfloat16(v);
    lo = __float2bfloat16(v - __bfloat162float(hi));
}

// ---------------- prep kernels ----------------------------------------------
__global__ __launch_bounds__(256)
void prep_w(const float* __restrict__ wih, const float* __restrict__ whh) {
    int idx = blockIdx.x * 256 + threadIdx.x;           // 0 .. 2*512*512-1
    int which = idx >> 18;
    int e = idx & 262143;
    int n = e >> 9, k = e & 511;
    const float* src = which ? whh : wih;
    __nv_bfloat16 hi, lo;
    split2(src[n * 512 + k], hi, lo);
    __nv_bfloat16* dst = g_ws[which] + (size_t)n * KSPLIT;
    dst[k] = hi; dst[512 + k] = lo; dst[1024 + k] = hi;
}

__global__ __launch_bounds__(256)
void prep_x(const float* __restrict__ x) {
    size_t idx = (size_t)blockIdx.x * 256 + threadIdx.x;  // over 65536*128 float4
    size_t row = idx >> 7;
    int q = (int)(idx & 127);
    float4 v = ((const float4*)x)[idx];
    __nv_bfloat16 h0,h1,h2,h3,l0,l1,l2,l3;
    split2(v.x,h0,l0); split2(v.y,h1,l1); split2(v.z,h2,l2); split2(v.w,h3,l3);
    __nv_bfloat16* base = g_xs + row * KSTORE + q * 4;
    *(__nv_bfloat162*)(base)       = __nv_bfloat162{h0,h1};
    *(__nv_bfloat162*)(base + 2)   = __nv_bfloat162{h2,h3};
    *(__nv_bfloat162*)(base + 512) = __nv_bfloat162{l0,l1};
    *(__nv_bfloat162*)(base + 514) = __nv_bfloat162{l2,l3};
}

// ---------------- bf16x3 HMMA GEMM ------------------------------------------
// C[m][n] = sum over K''=1536 of A''[m][k]*W''[n][k]; A'' chunk c maps to
// stored chunk (c<16 ? c : c-16) of the [hi|lo] layout.
// mode 0: g_pre = acc + bias; t=0 rows also write tanh-split H0
// mode 1: h = tanh(acc + pre_t); split-bf16 h out (fp32 out at t=7)
__global__ __launch_bounds__(256, 2)
void gemm_bf16x3(const __nv_bfloat16* __restrict__ A,
                 const __nv_bfloat16* __restrict__ Bw,
                 const float* __restrict__ b0, const float* __restrict__ b1,
                 float* __restrict__ outp, __nv_bfloat16* __restrict__ hs_out,
                 __nv_bfloat16* __restrict__ h0_out,
                 int mode, int t)
{
    extern __shared__ __align__(16) char dyn[];   // NSTAGE x [A:10240 | B:10240]
    __shared__ float s_bias[128];

    const int tid = threadIdx.x;
    const int wid = tid >> 5;
    const int lane = tid & 31;
    const int warpM = wid & 3;
    const int warpN = wid >> 2;
    const int bm = blockIdx.y * 128;
    const int bn = blockIdx.x * 128;

    const uint32_t sbase = smem_u32(dyn);

    if (mode == 0 && tid < 128) s_bias[tid] = b0[bn + tid] + b1[bn + tid];

    // Loader mapping: 512 16B-chunks per operand tile; thread does 2 A + 2 B.
    const int l_row0 = tid >> 2;            // rows 0..63
    const int l_row1 = l_row0 + 64;
    const int l_ch   = tid & 3;
    const uint4* A4 = (const uint4*)A;      // row stride 128 uint4 (KSTORE)
    const uint4* B4 = (const uint4*)Bw;     // row stride 192 uint4 (KSPLIT)

    const uint32_t sA0 = l_row0 * ROWB + l_ch * 16;
    const uint32_t sA1 = l_row1 * ROWB + l_ch * 16;
    const uint4* Ap0 = &A4[(size_t)(bm + l_row0) * 128 + l_ch];
    const uint4* Ap1 = &A4[(size_t)(bm + l_row1) * 128 + l_ch];
    const uint4* Bp0 = &B4[(size_t)(bn + l_row0) * 192 + l_ch];
    const uint4* Bp1 = &B4[(size_t)(bn + l_row1) * 192 + l_ch];

    // ldmatrix lane offsets
    const int g = lane >> 3;
    uint32_t a_off[2], b_off[4];
    #pragma unroll
    for (int mt = 0; mt < 2; mt++)
        a_off[mt] = (uint32_t)((warpM * 32 + mt * 16 + (g & 1) * 8 + (lane & 7)) * ROWB
                               + (g >> 1) * 16);
    #pragma unroll
    for (int np = 0; np < 4; np++)
        b_off[np] = (uint32_t)((warpN * 64 + np * 16 + (g >> 1) * 8 + (lane & 7)) * ROWB
                               + (g & 1) * 16);

    float acc[2][8][4];
    #pragma unroll
    for (int i = 0; i < 2; i++)
        #pragma unroll
        for (int j = 0; j < 8; j++)
            #pragma unroll
            for (int q = 0; q < 4; q++) acc[i][j][q] = 0.0f;

    // ---- prologue: fill stages 0..NSTAGE-2
    #pragma unroll
    for (int s = 0; s < NSTAGE - 1; s++) {
        const uint32_t st = sbase + s * STAGEB;
        const int ka = (s < 16 ? s : s - 16) * 4;
        const int kb = s * 4;
        cp16(st + sA0,         Ap0 + ka);
        cp16(st + sA1,         Ap1 + ka);
        cp16(st + TILEB + sA0, Bp0 + kb);
        cp16(st + TILEB + sA1, Bp1 + kb);
        cp_commit();
    }

    int st_cur = 0, st_nxt = NSTAGE - 1;
    for (int c = 0; c < NKIT; c++) {
        cp_wait<NSTAGE - 2>();
        __syncthreads();

        const int cn = c + NSTAGE - 1;
        if (cn < NKIT) {
            const uint32_t st = sbase + st_nxt * STAGEB;
            const int ka = (cn < 16 ? cn : cn - 16) * 4;
            const int kb = cn * 4;
            cp16(st + sA0,         Ap0 + ka);
            cp16(st + sA1,         Ap1 + ka);
            cp16(st + TILEB + sA0, Bp0 + kb);
            cp16(st + TILEB + sA1, Bp1 + kb);
        }
        cp_commit();   // unconditional: exact group accounting at the tail
        if (++st_nxt == NSTAGE) st_nxt = 0;

        const uint32_t ab = sbase + st_cur * STAGEB;
        const uint32_t bb = ab + TILEB;
        if (++st_cur == NSTAGE) st_cur = 0;

        #pragma unroll
        for (int kk = 0; kk < 2; kk++) {
            // Issue ALL loads of this kk-group first (6 ldmatrix back-to-back),
            // then all 16 mma — one scoreboard drain instead of eight.
            uint32_t afr[2][4];
            uint32_t bfr[4][4];
            #pragma unroll
            for (int mt = 0; mt < 2; mt++)
                ldsm4(afr[mt][0], afr[mt][1], afr[mt][2], afr[mt][3],
                      ab + a_off[mt] + kk * 32);
            #pragma unroll
            for (int np = 0; np < 4; np++)
                ldsm4(bfr[np][0], bfr[np][1], bfr[np][2], bfr[np][3],
                      bb + b_off[np] + kk * 32);
            #pragma unroll
            for (int np = 0; np < 4; np++) {
                #pragma unroll
                for (int mt = 0; mt < 2; mt++) {
                    mma16816(acc[mt][np * 2],     afr[mt], bfr[np][0], bfr[np][1]);
                    mma16816(acc[mt][np * 2 + 1], afr[mt], bfr[np][2], bfr[np][3]);
                }
            }
        }
    }

    // ---- epilogue --------------------------------------------------------
    const int r_in = lane >> 2;
    const int c_in = (lane & 3) * 2;
    #pragma unroll
    for (int mt = 0; mt < 2; mt++) {
        const int m0 = bm + warpM * 32 + mt * 16 + r_in;   // and m0+8
        #pragma unroll
        for (int nt = 0; nt < 8; nt++) {
            const int nb = bn + warpN * 64 + nt * 8 + c_in;
            float v00 = acc[mt][nt][0], v01 = acc[mt][nt][1];
            float v10 = acc[mt][nt][2], v11 = acc[mt][nt][3];
            if (mode == 0) {
                const float bia0 = s_bias[nb - bn], bia1 = s_bias[nb - bn + 1];
                v00 += bia0; v01 += bia1; v10 += bia0; v11 += bia1;
                *(float2*)(g_pre + (size_t)m0 * EDIM + nb)       = make_float2(v00, v01);
                *(float2*)(g_pre + (size_t)(m0 + 8) * EDIM + nb) = make_float2(v10, v11);
                if ((m0 & 7) == 0) {
                    #pragma unroll
                    for (int h = 0; h < 2; h++) {
                        const size_t w = (size_t)(m0 + 8 * h) >> 3;
                        float a0 = tanhf(h ? v10 : v00);
                        float a1 = tanhf(h ? v11 : v01);
                        __nv_bfloat16 x0,x1,y0,y1;
                        split2(a0, x0, y0); split2(a1, x1, y1);
                        __nv_bfloat16* hd = h0_out + w * KSTORE + nb;
                        *(__nv_bfloat162*)(hd)       = __nv_bfloat162{x0, x1};
                        *(__nv_bfloat162*)(hd + 512) = __nv_bfloat162{y0, y1};
                    }
                }
            } else {
                #pragma unroll
                for (int h = 0; h < 2; h++) {
                    const int m = m0 + 8 * h;
                    float2 pr = *(const float2*)(g_pre + ((size_t)m * TSTEPS + t) * EDIM + nb);
                    float a0 = tanhf((h ? v10 : v00) + pr.x);
                    float a1 = tanhf((h ? v11 : v01) + pr.y);
                    if (t == TSTEPS - 1) {
                        *(float2*)(outp + (size_t)m * EDIM + nb) = make_float2(a0, a1);
                    } else {
                        __nv_bfloat16 x0,x1,y0,y1;
                        split2(a0, x0, y0); split2(a1, x1, y1);
                        __nv_bfloat16* hd = hs_out + (size_t)m * KSTORE + nb;
                        *(__nv_bfloat162*)(hd)       = __nv_bfloat162{x0, x1};
                        *(__nv_bfloat162*)(hd + 512) = __nv_bfloat162{y0, y1};
                    }
                }
            }
        }
    }
}

// ---------------- host ------------------------------------------------------
extern "C" void kernel_launch(void* const* d_in, const int* in_sizes, int n_in,
                              void* d_out, int out_size)
{
    (void)in_sizes; (void)n_in; (void)out_size;
    const float* x    = (const float*)d_in[0];
    const float* W_ih = (const float*)d_in[1];
    const float* W_hh = (const float*)d_in[2];
    const float* b_ih = (const float*)d_in[3];
    const float* b_hh = (const float*)d_in[4];
    float* out = (float*)d_out;

    static __nv_bfloat16* p_xs = nullptr;
    static __nv_bfloat16* p_ws[2];
    static __nv_bfloat16* p_hs[2];
    if (!p_xs) {
        void* p;
        cudaGetSymbolAddress(&p, g_xs); p_xs = (__nv_bfloat16*)p;
        cudaGetSymbolAddress(&p, g_ws);
        p_ws[0] = (__nv_bfloat16*)p;
        p_ws[1] = p_ws[0] + (size_t)EDIM * KSPLIT;
        cudaGetSymbolAddress(&p, g_hs);
        p_hs[0] = (__nv_bfloat16*)p;
        p_hs[1] = p_hs[0] + (size_t)NWIN * KSTORE;
        cudaFuncSetAttribute(gemm_bf16x3,
                             cudaFuncAttributeMaxDynamicSharedMemorySize, SMEMB);
    }

    prep_w<<<2048, 256>>>(W_ih, W_hh);
    prep_x<<<32768, 256>>>(x);

    // pre = X'' @ Wih''^T + bias ; fused H0 for t=0 rows
    gemm_bf16x3<<<dim3(4, 512), 256, SMEMB>>>(p_xs, p_ws[0], b_ih, b_hh,
                                              nullptr, nullptr, p_hs[0], 0, 0);

    for (int t = 1; t < TSTEPS; t++) {
        gemm_bf16x3<<<dim3(4, 64), 256, SMEMB>>>(
            p_hs[(t - 1) & 1], p_ws[1], nullptr, nullptr,
            (t == TSTEPS - 1) ? out : nullptr, p_hs[t & 1], nullptr, 1, t);
    }
}